// round 13
// baseline (speedup 1.0000x reference)
#include <cuda_runtime.h>
#include <cuda_bf16.h>
#include <math.h>
#include <stdint.h>

#define DCH 128
#define MAXN 1000000
#define MAXS 16384
#define BKN 64             // nodes per tile in gate kernel
#define BN 128             // rows per block in out kernel
#define PAD 129
#define ASTRIDE 136        // padded bf16 row stride (elements); 272 bytes

// ---------------- scratch ----------------------------------------------------
__device__ float          g_gate[MAXN];
__device__ unsigned int   g_segmax[MAXS];
__device__ int            g_segstart[MAXS + 1];
__device__ float          g_pool[MAXS * DCH];
__device__ float          g_wsum[MAXS];
__device__ __nv_bfloat16  g_wthi[DCH * DCH];   // W^T hi  [n][k]
__device__ __nv_bfloat16  g_wtlo[DCH * DCH];   // W^T lo  [n][k]

__device__ __forceinline__ unsigned int enc_f32(float f) {
    unsigned int u = __float_as_uint(f);
    return (u & 0x80000000u) ? ~u : (u | 0x80000000u);
}
__device__ __forceinline__ float dec_f32(unsigned int e) {
    return (e & 0x80000000u) ? __uint_as_float(e ^ 0x80000000u)
                             : __uint_as_float(~e);
}

__device__ __forceinline__ uint32_t smem_u32(const void* p) {
    uint32_t a;
    asm("{ .reg .u64 t; cvta.to.shared.u64 t, %1; cvt.u32.u64 %0, t; }"
        : "=r"(a) : "l"(p));
    return a;
}

__device__ __forceinline__ void mma16816(float* d, const uint32_t* a,
                                         uint32_t b0, uint32_t b1) {
    asm volatile(
        "mma.sync.aligned.m16n8k16.row.col.f32.bf16.bf16.f32 "
        "{%0,%1,%2,%3}, {%4,%5,%6,%7}, {%8,%9}, {%0,%1,%2,%3};"
        : "+f"(d[0]), "+f"(d[1]), "+f"(d[2]), "+f"(d[3])
        : "r"(a[0]), "r"(a[1]), "r"(a[2]), "r"(a[3]), "r"(b0), "r"(b1));
}

#define LDSM_X4(r0, r1, r2, r3, addr) \
    asm volatile("ldmatrix.sync.aligned.m8n8.x4.shared.b16 {%0,%1,%2,%3}, [%4];" \
        : "=r"(r0), "=r"(r1), "=r"(r2), "=r"(r3) : "r"(addr))

// ---------------- K_w: split Wg1 into bf16 hi/lo, transposed [n][k] ----------
__global__ void wprep_kernel(const float* __restrict__ Wg1) {
    int idx = blockIdx.x * blockDim.x + threadIdx.x;
    if (idx >= DCH * DCH) return;
    int n = idx >> 7, k = idx & 127;
    float v = Wg1[k * DCH + n];
    __nv_bfloat16 hb = __float2bfloat16(v);
    __nv_bfloat16 lb = __float2bfloat16(v - __bfloat162float(hb));
    g_wthi[idx] = hb;
    g_wtlo[idx] = lb;
}

// ---------------- K0: init + segment starts ----------------------------------
__global__ void segstart_kernel(const int* __restrict__ batch, int N, int S) {
    int s = blockIdx.x * blockDim.x + threadIdx.x;
    if (s <= S) {
        int lo = 0, hi = N;
        while (lo < hi) {
            int mid = (lo + hi) >> 1;
            if (batch[mid] < s) lo = mid + 1; else hi = mid;
        }
        g_segstart[s] = lo;
    }
    if (s < S) g_segmax[s] = 0u;
}

// ---------------- K1: persistent gate kernel (bf16 split HMMA) ---------------
// 128 threads, 2 CTAs/SM, grid-stride over 64-node tiles. W resident in smem.
#define SM_XHI 0
#define SM_XLO (BKN * ASTRIDE)
#define SM_WHI (2 * BKN * ASTRIDE)
#define SM_WLO (2 * BKN * ASTRIDE + DCH * ASTRIDE)
#define SM_VEC (2 * BKN * ASTRIDE + 2 * DCH * ASTRIDE)   // bf16-elem offset of fp32 vec area
#define GATE_SMEM (SM_VEC * 2 + 1024 + 16)                // + bg1s/wg2s (512B each)

__global__ void __launch_bounds__(128, 2)
gate_mma_kernel(const float* __restrict__ x,
                const float* __restrict__ bg1,
                const float* __restrict__ wg2,
                const float* __restrict__ bg2,
                const int* __restrict__ batch,
                int N, int numTiles) {
    extern __shared__ __nv_bfloat16 sm[];
    __nv_bfloat16* xhi = sm + SM_XHI;
    __nv_bfloat16* xlo = sm + SM_XLO;
    __nv_bfloat16* whi = sm + SM_WHI;
    __nv_bfloat16* wlo = sm + SM_WLO;
    float* bg1s = (float*)(sm + SM_VEC);
    float* wg2s = bg1s + 128;

    const int tid = threadIdx.x;

    // ---- one-time: W^T hi/lo + bias/gate vectors into smem -------------------
    {
        const uint4* srch = (const uint4*)g_wthi;
        const uint4* srcl = (const uint4*)g_wtlo;
        #pragma unroll 4
        for (int i = tid; i < DCH * 16; i += 128) {
            int row = i >> 4, q = i & 15;
            *(uint4*)((char*)whi + row * (ASTRIDE * 2) + q * 16) = srch[i];
            *(uint4*)((char*)wlo + row * (ASTRIDE * 2) + q * 16) = srcl[i];
        }
        bg1s[tid] = bg1[tid];
        wg2s[tid] = wg2[tid];
    }
    const float b2 = bg2[0];

    const int lane = tid & 31, warp = tid >> 5;
    const int g = lane >> 2, tg = lane & 3;

    // ldmatrix lane addresses (fixed across tiles)
    uint32_t smb = smem_u32(sm);
    uint32_t a_row = (uint32_t)(warp * 16 + (lane & 15));
    uint32_t a_off = a_row * (ASTRIDE * 2) + ((uint32_t)(lane >> 4)) * 16u;
    uint32_t ahi_addr = smb + SM_XHI * 2 + a_off;
    uint32_t alo_addr = smb + SM_XLO * 2 + a_off;
    uint32_t b_row = (uint32_t)(((lane >> 4) << 3) + (lane & 7));
    uint32_t b_off = b_row * (ASTRIDE * 2) + ((uint32_t)((lane >> 3) & 1)) * 16u;
    uint32_t bhi_addr = smb + SM_WHI * 2 + b_off;
    uint32_t blo_addr = smb + SM_WLO * 2 + b_off;

    const float4* xg = (const float4*)x;

    for (int tile = blockIdx.x; tile < numTiles; tile += gridDim.x) {
        const int base = tile * BKN;

        // ---- stage x tile: fp32 -> bf16 hi/lo (previous readers done: sync at loop end)
        __syncthreads();
        #pragma unroll 4
        for (int i = tid; i < BKN * 32; i += 128) {
            int r = i >> 5, q = i & 31;
            float4 v = make_float4(0.f, 0.f, 0.f, 0.f);
            int node = base + r;
            if (node < N) v = xg[(size_t)node * 32 + q];
            __nv_bfloat16 h0 = __float2bfloat16(v.x);
            __nv_bfloat16 h1 = __float2bfloat16(v.y);
            __nv_bfloat16 h2 = __float2bfloat16(v.z);
            __nv_bfloat16 h3 = __float2bfloat16(v.w);
            __nv_bfloat16 l0 = __float2bfloat16(v.x - __bfloat162float(h0));
            __nv_bfloat16 l1 = __float2bfloat16(v.y - __bfloat162float(h1));
            __nv_bfloat16 l2 = __float2bfloat16(v.z - __bfloat162float(h2));
            __nv_bfloat16 l3 = __float2bfloat16(v.w - __bfloat162float(h3));
            uint32_t hA = ((uint32_t)__bfloat16_as_ushort(h1) << 16) | __bfloat16_as_ushort(h0);
            uint32_t hB = ((uint32_t)__bfloat16_as_ushort(h3) << 16) | __bfloat16_as_ushort(h2);
            uint32_t lA = ((uint32_t)__bfloat16_as_ushort(l1) << 16) | __bfloat16_as_ushort(l0);
            uint32_t lB = ((uint32_t)__bfloat16_as_ushort(l3) << 16) | __bfloat16_as_ushort(l2);
            *(uint2*)((char*)xhi + r * (ASTRIDE * 2) + q * 8) = make_uint2(hA, hB);
            *(uint2*)((char*)xlo + r * (ASTRIDE * 2) + q * 8) = make_uint2(lA, lB);
        }
        __syncthreads();

        // ---- mma mainloop: 3-term bf16 split --------------------------------
        float acc[16][4];
        #pragma unroll
        for (int t = 0; t < 16; t++)
            #pragma unroll
            for (int c = 0; c < 4; c++) acc[t][c] = 0.f;

        #pragma unroll
        for (int ks = 0; ks < 8; ks++) {
            uint32_t koff = (uint32_t)ks * 32u;
            uint32_t ah[4], al[4];
            LDSM_X4(ah[0], ah[1], ah[2], ah[3], ahi_addr + koff);
            LDSM_X4(al[0], al[1], al[2], al[3], alo_addr + koff);

            uint32_t b[16][2];
            #pragma unroll
            for (int tt = 0; tt < 8; tt++)
                LDSM_X4(b[2*tt][0], b[2*tt][1], b[2*tt+1][0], b[2*tt+1][1],
                        bhi_addr + koff + (uint32_t)tt * (16u * ASTRIDE * 2u));
            #pragma unroll
            for (int t = 0; t < 16; t++) mma16816(acc[t], ah, b[t][0], b[t][1]);
            #pragma unroll
            for (int t = 0; t < 16; t++) mma16816(acc[t], al, b[t][0], b[t][1]);

            #pragma unroll
            for (int tt = 0; tt < 8; tt++)
                LDSM_X4(b[2*tt][0], b[2*tt][1], b[2*tt+1][0], b[2*tt+1][1],
                        blo_addr + koff + (uint32_t)tt * (16u * ASTRIDE * 2u));
            #pragma unroll
            for (int t = 0; t < 16; t++) mma16816(acc[t], ah, b[t][0], b[t][1]);
        }

        // ---- epilogue: gate = relu(h + bg1) . wg2 + bg2 ----------------------
        float s0 = 0.f, s1 = 0.f;
        #pragma unroll
        for (int t = 0; t < 16; t++) {
            int c = t * 8 + tg * 2;
            float b0v = bg1s[c], b1v = bg1s[c + 1];
            float w0v = wg2s[c], w1v = wg2s[c + 1];
            s0 += fmaxf(acc[t][0] + b0v, 0.f) * w0v + fmaxf(acc[t][1] + b1v, 0.f) * w1v;
            s1 += fmaxf(acc[t][2] + b0v, 0.f) * w0v + fmaxf(acc[t][3] + b1v, 0.f) * w1v;
        }
        s0 += __shfl_xor_sync(0xffffffffu, s0, 1);
        s0 += __shfl_xor_sync(0xffffffffu, s0, 2);
        s1 += __shfl_xor_sync(0xffffffffu, s1, 1);
        s1 += __shfl_xor_sync(0xffffffffu, s1, 2);

        if (tg == 0) {
            int n0 = base + warp * 16 + g;
            int n1 = n0 + 8;
            if (n0 < N) {
                float gv = s0 + b2;
                g_gate[n0] = gv;
                atomicMax(&g_segmax[batch[n0]], enc_f32(gv));
            }
            if (n1 < N) {
                float gv = s1 + b2;
                g_gate[n1] = gv;
                atomicMax(&g_segmax[batch[n1]], enc_f32(gv));
            }
        }
    }
}

// ---------------- K3: fused exp + weighted pooling (one CTA per segment) -----
__global__ void pool_kernel(const float* __restrict__ x, int S) {
    int s = blockIdx.x;
    int c = threadIdx.x;
    int beg = g_segstart[s];
    int end = g_segstart[s + 1];

    __shared__ float ev[128];
    __shared__ float red[4];

    float m = (beg < end) ? dec_f32(g_segmax[s]) : 0.f;
    float acc = 0.f, dpart = 0.f;

    for (int tile = beg; tile < end; tile += 128) {
        int nid = tile + c;
        float e = 0.f;
        if (nid < end) e = expf(g_gate[nid] - m);
        __syncthreads();
        ev[c] = e;
        dpart += e;
        __syncthreads();
        int len = min(128, end - tile);
        int j = 0;
        for (; j + 3 < len; j += 4) {
            acc += ev[j]     * x[(size_t)(tile + j)     * DCH + c];
            acc += ev[j + 1] * x[(size_t)(tile + j + 1) * DCH + c];
            acc += ev[j + 2] * x[(size_t)(tile + j + 2) * DCH + c];
            acc += ev[j + 3] * x[(size_t)(tile + j + 3) * DCH + c];
        }
        for (; j < len; j++)
            acc += ev[j] * x[(size_t)(tile + j) * DCH + c];
    }

    #pragma unroll
    for (int o = 16; o; o >>= 1) dpart += __shfl_xor_sync(0xffffffffu, dpart, o);
    if ((c & 31) == 0) red[c >> 5] = dpart;
    __syncthreads();
    float denom = red[0] + red[1] + red[2] + red[3];
    float inv = 1.0f / (denom + 1e-16f);

    g_pool[s * DCH + c] = acc * inv;
    if (c == 0) g_wsum[s] = denom * inv;
}

// ---------------- K4: out = pool @ Wn + wsum*bn -------------------------------
__global__ void out_kernel(const float* __restrict__ Wn,
                           const float* __restrict__ bn,
                           float* __restrict__ out, int S) {
    extern __shared__ float smf[];
    float* Ws = smf;
    float* Xs = smf + DCH * DCH;

    int tid = threadIdx.x;
    int base = blockIdx.x * BN;

    const float4* W4 = (const float4*)Wn;
    float4* Ws4 = (float4*)Ws;
    #pragma unroll 4
    for (int i = tid; i < DCH * (DCH / 4); i += 256) Ws4[i] = W4[i];

    for (int i = tid; i < BN * (DCH / 4); i += 256) {
        int row = i >> 5;
        int kq  = i & 31;
        float4 v = ((const float4*)g_pool)[(size_t)(base + row) * (DCH / 4) + kq];
        float* dst = &Xs[row * PAD + kq * 4];
        dst[0] = v.x; dst[1] = v.y; dst[2] = v.z; dst[3] = v.w;
    }
    __syncthreads();

    int ty = tid >> 4;
    int tx = tid & 15;

    float acc[8][8];
    #pragma unroll
    for (int i = 0; i < 8; i++)
        #pragma unroll
        for (int j = 0; j < 8; j++) acc[i][j] = 0.f;

    #pragma unroll 4
    for (int k = 0; k < DCH; k++) {
        float xv[8];
        #pragma unroll
        for (int i = 0; i < 8; i++) xv[i] = Xs[(ty * 8 + i) * PAD + k];
        float4 w0 = *(const float4*)&Ws[k * DCH + tx * 8];
        float4 w1 = *(const float4*)&Ws[k * DCH + tx * 8 + 4];
        float wv[8] = {w0.x, w0.y, w0.z, w0.w, w1.x, w1.y, w1.z, w1.w};
        #pragma unroll
        for (int i = 0; i < 8; i++)
            #pragma unroll
            for (int j = 0; j < 8; j++) acc[i][j] += xv[i] * wv[j];
    }

    float bnj[8];
    #pragma unroll
    for (int j = 0; j < 8; j++) bnj[j] = bn[tx * 8 + j];

    #pragma unroll
    for (int i = 0; i < 8; i++) {
        int row = base + ty * 8 + i;
        float ws = g_wsum[row];
        #pragma unroll
        for (int j = 0; j < 8; j++)
            out[(size_t)row * DCH + tx * 8 + j] = acc[i][j] + ws * bnj[j];
    }
}

// ---------------- launch ------------------------------------------------------
extern "C" void kernel_launch(void* const* d_in, const int* in_sizes, int n_in,
                              void* d_out, int out_size) {
    const float* x     = (const float*)d_in[0];
    const int*   batch = (const int*)d_in[1];
    const float* Wg1   = (const float*)d_in[2];
    const float* bg1   = (const float*)d_in[3];
    const float* wg2   = (const float*)d_in[4];
    const float* bg2   = (const float*)d_in[5];
    const float* Wn    = (const float*)d_in[6];
    const float* bn    = (const float*)d_in[7];
    float* out = (float*)d_out;

    int N = in_sizes[1];
    int S = out_size / DCH;
    int numTiles = (N + BKN - 1) / BKN;

    size_t smem_out = (DCH * DCH + BN * PAD) * sizeof(float);
    cudaFuncSetAttribute(out_kernel, cudaFuncAttributeMaxDynamicSharedMemorySize, (int)smem_out);
    cudaFuncSetAttribute(gate_mma_kernel, cudaFuncAttributeMaxDynamicSharedMemorySize, GATE_SMEM);

    // prep (independent)
    wprep_kernel<<<(DCH * DCH + 255) / 256, 256>>>(Wg1);
    segstart_kernel<<<(S + 1 + 255) / 256, 256>>>(batch, N, S);

    // persistent gate GEMM on HMMA tensor cores (bf16 3-term split)
    int gateGrid = 296;             // 2 CTAs per SM on 148 SMs
    if (gateGrid > numTiles) gateGrid = numTiles;
    gate_mma_kernel<<<gateGrid, 128, GATE_SMEM>>>(x, bg1, wg2, bg2, batch, N, numTiles);

    // fused exp + weighted pooling in x-space
    pool_kernel<<<S, DCH>>>(x, S);

    // final small GEMM + bias
    out_kernel<<<S / BN, 256, smem_out>>>(Wn, bn, out, S);
}

// round 14
// speedup vs baseline: 1.0010x; 1.0010x over previous
#include <cuda_runtime.h>
#include <cuda_bf16.h>
#include <math.h>
#include <stdint.h>

#define DCH 128
#define MAXN 1000000
#define MAXS 16384
#define BKN 64             // nodes per tile in gate kernel
#define BN 128             // rows per block in out kernel
#define PAD 129
#define ASTRIDE 136        // padded bf16 row stride (elements); 272 bytes

// ---------------- scratch ----------------------------------------------------
__device__ float          g_gate[MAXN];
__device__ unsigned int   g_segmax[MAXS];
__device__ int            g_segstart[MAXS + 1];
__device__ float          g_pool[MAXS * DCH];
__device__ float          g_wsum[MAXS];
__device__ __nv_bfloat16  g_wthi[DCH * DCH];   // W^T hi  [n][k]
__device__ __nv_bfloat16  g_wtlo[DCH * DCH];   // W^T lo  [n][k]

__device__ __forceinline__ unsigned int enc_f32(float f) {
    unsigned int u = __float_as_uint(f);
    return (u & 0x80000000u) ? ~u : (u | 0x80000000u);
}
__device__ __forceinline__ float dec_f32(unsigned int e) {
    return (e & 0x80000000u) ? __uint_as_float(e ^ 0x80000000u)
                             : __uint_as_float(~e);
}

__device__ __forceinline__ uint32_t smem_u32(const void* p) {
    uint32_t a;
    asm("{ .reg .u64 t; cvta.to.shared.u64 t, %1; cvt.u32.u64 %0, t; }"
        : "=r"(a) : "l"(p));
    return a;
}

__device__ __forceinline__ void mma16816(float* d, const uint32_t* a,
                                         uint32_t b0, uint32_t b1) {
    asm volatile(
        "mma.sync.aligned.m16n8k16.row.col.f32.bf16.bf16.f32 "
        "{%0,%1,%2,%3}, {%4,%5,%6,%7}, {%8,%9}, {%0,%1,%2,%3};"
        : "+f"(d[0]), "+f"(d[1]), "+f"(d[2]), "+f"(d[3])
        : "r"(a[0]), "r"(a[1]), "r"(a[2]), "r"(a[3]), "r"(b0), "r"(b1));
}

#define LDSM_X4(r0, r1, r2, r3, addr) \
    asm volatile("ldmatrix.sync.aligned.m8n8.x4.shared.b16 {%0,%1,%2,%3}, [%4];" \
        : "=r"(r0), "=r"(r1), "=r"(r2), "=r"(r3) : "r"(addr))

// ---------------- K_w: split Wg1 into bf16 hi/lo, transposed [n][k] ----------
__global__ void wprep_kernel(const float* __restrict__ Wg1) {
    int idx = blockIdx.x * blockDim.x + threadIdx.x;
    if (idx >= DCH * DCH) return;
    int n = idx >> 7, k = idx & 127;
    float v = Wg1[k * DCH + n];
    __nv_bfloat16 hb = __float2bfloat16(v);
    __nv_bfloat16 lb = __float2bfloat16(v - __bfloat162float(hb));
    g_wthi[idx] = hb;
    g_wtlo[idx] = lb;
}

// ---------------- K0: init + segment starts ----------------------------------
__global__ void segstart_kernel(const int* __restrict__ batch, int N, int S) {
    int s = blockIdx.x * blockDim.x + threadIdx.x;
    if (s <= S) {
        int lo = 0, hi = N;
        while (lo < hi) {
            int mid = (lo + hi) >> 1;
            if (batch[mid] < s) lo = mid + 1; else hi = mid;
        }
        g_segstart[s] = lo;
    }
    if (s < S) g_segmax[s] = 0u;
}

// ---------------- K1: persistent gate kernel (bf16 split HMMA) ---------------
// 128 threads, 2 CTAs/SM, grid-stride over 64-node tiles. W resident in smem.
#define SM_XHI 0
#define SM_XLO (BKN * ASTRIDE)
#define SM_WHI (2 * BKN * ASTRIDE)
#define SM_WLO (2 * BKN * ASTRIDE + DCH * ASTRIDE)
#define SM_VEC (2 * BKN * ASTRIDE + 2 * DCH * ASTRIDE)   // bf16-elem offset of fp32 vec area
#define GATE_SMEM (SM_VEC * 2 + 1024 + 16)                // + bg1s/wg2s (512B each)

__global__ void __launch_bounds__(128, 2)
gate_mma_kernel(const float* __restrict__ x,
                const float* __restrict__ bg1,
                const float* __restrict__ wg2,
                const float* __restrict__ bg2,
                const int* __restrict__ batch,
                int N, int numTiles) {
    extern __shared__ __nv_bfloat16 sm[];
    __nv_bfloat16* xhi = sm + SM_XHI;
    __nv_bfloat16* xlo = sm + SM_XLO;
    __nv_bfloat16* whi = sm + SM_WHI;
    __nv_bfloat16* wlo = sm + SM_WLO;
    float* bg1s = (float*)(sm + SM_VEC);
    float* wg2s = bg1s + 128;

    const int tid = threadIdx.x;

    // ---- one-time: W^T hi/lo + bias/gate vectors into smem -------------------
    {
        const uint4* srch = (const uint4*)g_wthi;
        const uint4* srcl = (const uint4*)g_wtlo;
        #pragma unroll 4
        for (int i = tid; i < DCH * 16; i += 128) {
            int row = i >> 4, q = i & 15;
            *(uint4*)((char*)whi + row * (ASTRIDE * 2) + q * 16) = srch[i];
            *(uint4*)((char*)wlo + row * (ASTRIDE * 2) + q * 16) = srcl[i];
        }
        bg1s[tid] = bg1[tid];
        wg2s[tid] = wg2[tid];
    }
    const float b2 = bg2[0];

    const int lane = tid & 31, warp = tid >> 5;
    const int g = lane >> 2, tg = lane & 3;

    // ldmatrix lane addresses (fixed across tiles)
    uint32_t smb = smem_u32(sm);
    uint32_t a_row = (uint32_t)(warp * 16 + (lane & 15));
    uint32_t a_off = a_row * (ASTRIDE * 2) + ((uint32_t)(lane >> 4)) * 16u;
    uint32_t ahi_addr = smb + SM_XHI * 2 + a_off;
    uint32_t alo_addr = smb + SM_XLO * 2 + a_off;
    uint32_t b_row = (uint32_t)(((lane >> 4) << 3) + (lane & 7));
    uint32_t b_off = b_row * (ASTRIDE * 2) + ((uint32_t)((lane >> 3) & 1)) * 16u;
    uint32_t bhi_addr = smb + SM_WHI * 2 + b_off;
    uint32_t blo_addr = smb + SM_WLO * 2 + b_off;

    const float4* xg = (const float4*)x;

    for (int tile = blockIdx.x; tile < numTiles; tile += gridDim.x) {
        const int base = tile * BKN;

        // ---- stage x tile: fp32 -> bf16 hi/lo (previous readers done: sync at loop end)
        __syncthreads();
        #pragma unroll 4
        for (int i = tid; i < BKN * 32; i += 128) {
            int r = i >> 5, q = i & 31;
            float4 v = make_float4(0.f, 0.f, 0.f, 0.f);
            int node = base + r;
            if (node < N) v = xg[(size_t)node * 32 + q];
            __nv_bfloat16 h0 = __float2bfloat16(v.x);
            __nv_bfloat16 h1 = __float2bfloat16(v.y);
            __nv_bfloat16 h2 = __float2bfloat16(v.z);
            __nv_bfloat16 h3 = __float2bfloat16(v.w);
            __nv_bfloat16 l0 = __float2bfloat16(v.x - __bfloat162float(h0));
            __nv_bfloat16 l1 = __float2bfloat16(v.y - __bfloat162float(h1));
            __nv_bfloat16 l2 = __float2bfloat16(v.z - __bfloat162float(h2));
            __nv_bfloat16 l3 = __float2bfloat16(v.w - __bfloat162float(h3));
            uint32_t hA = ((uint32_t)__bfloat16_as_ushort(h1) << 16) | __bfloat16_as_ushort(h0);
            uint32_t hB = ((uint32_t)__bfloat16_as_ushort(h3) << 16) | __bfloat16_as_ushort(h2);
            uint32_t lA = ((uint32_t)__bfloat16_as_ushort(l1) << 16) | __bfloat16_as_ushort(l0);
            uint32_t lB = ((uint32_t)__bfloat16_as_ushort(l3) << 16) | __bfloat16_as_ushort(l2);
            *(uint2*)((char*)xhi + r * (ASTRIDE * 2) + q * 8) = make_uint2(hA, hB);
            *(uint2*)((char*)xlo + r * (ASTRIDE * 2) + q * 8) = make_uint2(lA, lB);
        }
        __syncthreads();

        // ---- mma mainloop: 3-term bf16 split --------------------------------
        float acc[16][4];
        #pragma unroll
        for (int t = 0; t < 16; t++)
            #pragma unroll
            for (int c = 0; c < 4; c++) acc[t][c] = 0.f;

        #pragma unroll
        for (int ks = 0; ks < 8; ks++) {
            uint32_t koff = (uint32_t)ks * 32u;
            uint32_t ah[4], al[4];
            LDSM_X4(ah[0], ah[1], ah[2], ah[3], ahi_addr + koff);
            LDSM_X4(al[0], al[1], al[2], al[3], alo_addr + koff);

            uint32_t b[16][2];
            #pragma unroll
            for (int tt = 0; tt < 8; tt++)
                LDSM_X4(b[2*tt][0], b[2*tt][1], b[2*tt+1][0], b[2*tt+1][1],
                        bhi_addr + koff + (uint32_t)tt * (16u * ASTRIDE * 2u));
            #pragma unroll
            for (int t = 0; t < 16; t++) mma16816(acc[t], ah, b[t][0], b[t][1]);
            #pragma unroll
            for (int t = 0; t < 16; t++) mma16816(acc[t], al, b[t][0], b[t][1]);

            #pragma unroll
            for (int tt = 0; tt < 8; tt++)
                LDSM_X4(b[2*tt][0], b[2*tt][1], b[2*tt+1][0], b[2*tt+1][1],
                        blo_addr + koff + (uint32_t)tt * (16u * ASTRIDE * 2u));
            #pragma unroll
            for (int t = 0; t < 16; t++) mma16816(acc[t], ah, b[t][0], b[t][1]);
        }

        // ---- epilogue: gate = relu(h + bg1) . wg2 + bg2 ----------------------
        float s0 = 0.f, s1 = 0.f;
        #pragma unroll
        for (int t = 0; t < 16; t++) {
            int c = t * 8 + tg * 2;
            float b0v = bg1s[c], b1v = bg1s[c + 1];
            float w0v = wg2s[c], w1v = wg2s[c + 1];
            s0 += fmaxf(acc[t][0] + b0v, 0.f) * w0v + fmaxf(acc[t][1] + b1v, 0.f) * w1v;
            s1 += fmaxf(acc[t][2] + b0v, 0.f) * w0v + fmaxf(acc[t][3] + b1v, 0.f) * w1v;
        }
        s0 += __shfl_xor_sync(0xffffffffu, s0, 1);
        s0 += __shfl_xor_sync(0xffffffffu, s0, 2);
        s1 += __shfl_xor_sync(0xffffffffu, s1, 1);
        s1 += __shfl_xor_sync(0xffffffffu, s1, 2);

        if (tg == 0) {
            int n0 = base + warp * 16 + g;
            int n1 = n0 + 8;
            if (n0 < N) {
                float gv = s0 + b2;
                g_gate[n0] = gv;
                atomicMax(&g_segmax[batch[n0]], enc_f32(gv));
            }
            if (n1 < N) {
                float gv = s1 + b2;
                g_gate[n1] = gv;
                atomicMax(&g_segmax[batch[n1]], enc_f32(gv));
            }
        }
    }
}

// ---------------- K3: fused exp + weighted pooling (one CTA per segment) -----
__global__ void pool_kernel(const float* __restrict__ x, int S) {
    int s = blockIdx.x;
    int c = threadIdx.x;
    int beg = g_segstart[s];
    int end = g_segstart[s + 1];

    __shared__ float ev[128];
    __shared__ float red[4];

    float m = (beg < end) ? dec_f32(g_segmax[s]) : 0.f;
    float acc = 0.f, dpart = 0.f;

    for (int tile = beg; tile < end; tile += 128) {
        int nid = tile + c;
        float e = 0.f;
        if (nid < end) e = expf(g_gate[nid] - m);
        __syncthreads();
        ev[c] = e;
        dpart += e;
        __syncthreads();
        int len = min(128, end - tile);
        int j = 0;
        for (; j + 3 < len; j += 4) {
            acc += ev[j]     * x[(size_t)(tile + j)     * DCH + c];
            acc += ev[j + 1] * x[(size_t)(tile + j + 1) * DCH + c];
            acc += ev[j + 2] * x[(size_t)(tile + j + 2) * DCH + c];
            acc += ev[j + 3] * x[(size_t)(tile + j + 3) * DCH + c];
        }
        for (; j < len; j++)
            acc += ev[j] * x[(size_t)(tile + j) * DCH + c];
    }

    #pragma unroll
    for (int o = 16; o; o >>= 1) dpart += __shfl_xor_sync(0xffffffffu, dpart, o);
    if ((c & 31) == 0) red[c >> 5] = dpart;
    __syncthreads();
    float denom = red[0] + red[1] + red[2] + red[3];
    float inv = 1.0f / (denom + 1e-16f);

    g_pool[s * DCH + c] = acc * inv;
    if (c == 0) g_wsum[s] = denom * inv;
}

// ---------------- K4: out = pool @ Wn + wsum*bn -------------------------------
__global__ void out_kernel(const float* __restrict__ Wn,
                           const float* __restrict__ bn,
                           float* __restrict__ out, int S) {
    extern __shared__ float smf[];
    float* Ws = smf;
    float* Xs = smf + DCH * DCH;

    int tid = threadIdx.x;
    int base = blockIdx.x * BN;

    const float4* W4 = (const float4*)Wn;
    float4* Ws4 = (float4*)Ws;
    #pragma unroll 4
    for (int i = tid; i < DCH * (DCH / 4); i += 256) Ws4[i] = W4[i];

    for (int i = tid; i < BN * (DCH / 4); i += 256) {
        int row = i >> 5;
        int kq  = i & 31;
        float4 v = ((const float4*)g_pool)[(size_t)(base + row) * (DCH / 4) + kq];
        float* dst = &Xs[row * PAD + kq * 4];
        dst[0] = v.x; dst[1] = v.y; dst[2] = v.z; dst[3] = v.w;
    }
    __syncthreads();

    int ty = tid >> 4;
    int tx = tid & 15;

    float acc[8][8];
    #pragma unroll
    for (int i = 0; i < 8; i++)
        #pragma unroll
        for (int j = 0; j < 8; j++) acc[i][j] = 0.f;

    #pragma unroll 4
    for (int k = 0; k < DCH; k++) {
        float xv[8];
        #pragma unroll
        for (int i = 0; i < 8; i++) xv[i] = Xs[(ty * 8 + i) * PAD + k];
        float4 w0 = *(const float4*)&Ws[k * DCH + tx * 8];
        float4 w1 = *(const float4*)&Ws[k * DCH + tx * 8 + 4];
        float wv[8] = {w0.x, w0.y, w0.z, w0.w, w1.x, w1.y, w1.z, w1.w};
        #pragma unroll
        for (int i = 0; i < 8; i++)
            #pragma unroll
            for (int j = 0; j < 8; j++) acc[i][j] += xv[i] * wv[j];
    }

    float bnj[8];
    #pragma unroll
    for (int j = 0; j < 8; j++) bnj[j] = bn[tx * 8 + j];

    #pragma unroll
    for (int i = 0; i < 8; i++) {
        int row = base + ty * 8 + i;
        float ws = g_wsum[row];
        #pragma unroll
        for (int j = 0; j < 8; j++)
            out[(size_t)row * DCH + tx * 8 + j] = acc[i][j] + ws * bnj[j];
    }
}

// ---------------- launch ------------------------------------------------------
extern "C" void kernel_launch(void* const* d_in, const int* in_sizes, int n_in,
                              void* d_out, int out_size) {
    const float* x     = (const float*)d_in[0];
    const int*   batch = (const int*)d_in[1];
    const float* Wg1   = (const float*)d_in[2];
    const float* bg1   = (const float*)d_in[3];
    const float* wg2   = (const float*)d_in[4];
    const float* bg2   = (const float*)d_in[5];
    const float* Wn    = (const float*)d_in[6];
    const float* bn    = (const float*)d_in[7];
    float* out = (float*)d_out;

    int N = in_sizes[1];
    int S = out_size / DCH;
    int numTiles = (N + BKN - 1) / BKN;

    size_t smem_out = (DCH * DCH + BN * PAD) * sizeof(float);
    cudaFuncSetAttribute(out_kernel, cudaFuncAttributeMaxDynamicSharedMemorySize, (int)smem_out);
    cudaFuncSetAttribute(gate_mma_kernel, cudaFuncAttributeMaxDynamicSharedMemorySize, GATE_SMEM);

    // prep (independent)
    wprep_kernel<<<(DCH * DCH + 255) / 256, 256>>>(Wg1);
    segstart_kernel<<<(S + 1 + 255) / 256, 256>>>(batch, N, S);

    // persistent gate GEMM on HMMA tensor cores (bf16 3-term split)
    int gateGrid = 296;             // 2 CTAs per SM on 148 SMs
    if (gateGrid > numTiles) gateGrid = numTiles;
    gate_mma_kernel<<<gateGrid, 128, GATE_SMEM>>>(x, bg1, wg2, bg2, batch, N, numTiles);

    // fused exp + weighted pooling in x-space
    pool_kernel<<<S, DCH>>>(x, S);

    // final small GEMM + bias
    out_kernel<<<S / BN, 256, smem_out>>>(Wn, bn, out, S);
}